// round 12
// baseline (speedup 1.0000x reference)
#include <cuda_runtime.h>
#include <cuda.h>
#include <cstdint>

// TCL-without-parameters loss, GB300 sm_103a (compiled as compute_103).
// score[b,c] = 0.5*||center_c||^2 - f_b . center_c   (0.5||f||^2 cancels in pos-neg)
// loss = mean relu(score[lab] + 5 - min_{c!=lab} score[c])
//
// R12: TMA staging (256-row x 32-col chunks, SW128) + mma.sync tf32.
// 16 consumer warps + 1 TMA producer warp; B pre-packed in fragment order (u64).

#define MARGIN_F 5.0f

constexpr int D      = 512;
constexpr int C      = 21;
constexpr int TILE_M = 256;         // rows per supertile (and per TMA chunk)
constexpr int KC     = 32;          // k-cols per chunk (128B rows -> SW128 atom)
constexpr int NCH    = D / KC;      // 16
constexpr int S      = 5;           // stage ring depth
constexpr int TPB    = 544;         // warps 0-15 consumers, warp 16 TMA producer
constexpr int GRID   = 148;

constexpr int STAGE_BYTES = TILE_M * KC * 4;   // 32768
constexpr int NFRAG = NCH * 4 * 3 * 32;        // B fragment u64 slots = 6144

// dynamic smem byte offsets
constexpr int SM_FULL  = 0;                     // S mbars
constexpr int SM_EMPTY = 64;                    // S mbars
constexpr int SM_C2    = 128;                   // 32 floats
constexpr int SM_FLAG  = 256;                   // label dtype flag
constexpr int SM_WSUM  = 288;                   // 17 floats
constexpr int SM_B     = 512;                   // NFRAG u64 = 49152 B
constexpr int SM_A     = 50176;                 // 1024-aligned; S stages
constexpr int SMEM_TOTAL = SM_A + S * STAGE_BYTES;   // 214016

__device__ float g_partials[256];
__device__ unsigned int g_counter = 0;

// ---------- device helpers ----------
__device__ __forceinline__ uint32_t smem_u32(const void* p) {
    return (uint32_t)__cvta_generic_to_shared(p);
}
#define SW128(o) ((uint32_t)(o) ^ ((((uint32_t)(o)) >> 3) & 0x70u))

#define MBARRIER_INIT(addr, cnt) \
    asm volatile("mbarrier.init.shared.b64 [%0], %1;" :: "r"((uint32_t)(addr)), "r"((uint32_t)(cnt)) : "memory")
#define MBARRIER_ARRIVE(addr) \
    asm volatile("mbarrier.arrive.shared.b64 _, [%0];" :: "r"((uint32_t)(addr)) : "memory")
#define MBARRIER_EXPECT_TX(addr, bytes) \
    asm volatile("mbarrier.arrive.expect_tx.shared.b64 _, [%0], %1;" :: "r"((uint32_t)(addr)), "r"((uint32_t)(bytes)) : "memory")
#define FENCE_PROXY_ASYNC() asm volatile("fence.proxy.async.shared::cta;" ::: "memory")

#define MBARRIER_WAIT_PARITY(addr, par) do {                                        \
    uint32_t _mbar = (uint32_t)(addr);                                              \
    uint32_t _par  = (uint32_t)(par);                                               \
    uint32_t _done;                                                                 \
    asm volatile("{\n\t.reg .pred p;\n\t"                                           \
        "mbarrier.try_wait.parity.shared.b64 p, [%1], %2;\n\t"                      \
        "selp.b32 %0, 1, 0, p;\n\t}"                                                \
        : "=r"(_done) : "r"(_mbar), "r"(_par) : "memory");                          \
    if (!_done) {                                                                   \
        asm volatile("{\n\t.reg .pred P1;\n\t"                                      \
            "WAIT_LOOP_%=:\n\t"                                                     \
            "mbarrier.try_wait.parity.shared.b64 P1, [%0], %1;\n\t"                 \
            "@P1 bra.uni WAIT_DONE_%=;\n\t"                                         \
            "bra.uni WAIT_LOOP_%=;\n\t"                                             \
            "WAIT_DONE_%=:\n\t}"                                                    \
            :: "r"(_mbar), "r"(_par) : "memory");                                   \
    }                                                                               \
} while (0)

__device__ __forceinline__ uint32_t f2tf32(float x) {
    uint32_t r;
    asm("cvt.rna.tf32.f32 %0, %1;" : "=r"(r) : "f"(x));
    return r;
}

__device__ __forceinline__ void mma_tf32(float d[4], uint32_t a0, uint32_t a1,
                                         uint32_t a2, uint32_t a3,
                                         uint32_t b0, uint32_t b1) {
    asm volatile(
        "mma.sync.aligned.m16n8k8.row.col.f32.tf32.tf32.f32 "
        "{%0,%1,%2,%3}, {%4,%5,%6,%7}, {%8,%9}, {%0,%1,%2,%3};"
        : "+f"(d[0]), "+f"(d[1]), "+f"(d[2]), "+f"(d[3])
        : "r"(a0), "r"(a1), "r"(a2), "r"(a3), "r"(b0), "r"(b1));
}

// ---------- kernel ----------
__global__ __launch_bounds__(TPB, 1)
void tcl_mma_kernel(const __grid_constant__ CUtensorMap tmap,
                    const float* __restrict__ centers,
                    const void* __restrict__ labels,
                    float* __restrict__ out,
                    int Btot, int ntiles) {
    extern __shared__ __align__(1024) char smemc[];
    const uint32_t sb = smem_u32(smemc);
    const int tid = threadIdx.x, wid = tid >> 5, lane = tid & 31;
    const int q = lane & 3, g4 = lane >> 2;
    const int bid = blockIdx.x;

    __shared__ unsigned int is_last;

    if (tid == 0) {
        #pragma unroll
        for (int s = 0; s < S; s++) {
            MBARRIER_INIT(sb + SM_FULL  + s * 8, 1);    // completes via TMA tx
            MBARRIER_INIT(sb + SM_EMPTY + s * 8, 16);   // 16 consumer warps
        }
        FENCE_PROXY_ASYNC();                            // barriers visible to async proxy
        // label dtype sniff: int64 labels (<2^32) have all-zero odd int32 words
        const int* lw = (const int*)labels;
        int i64 = 1;
        for (int i = 1; i < 128; i += 2) if (lw[i] != 0) { i64 = 0; break; }
        *(int*)(smemc + SM_FLAG) = i64;
    }

    // ---- B: centers -> tf32 fragment-ordered u64 {b0,b1} per (ch,ks,nt,lane) ----
    unsigned long long* Bf = (unsigned long long*)(smemc + SM_B);
    for (int i = tid; i < NFRAG; i += TPB) {
        const int ln = i & 31;
        int rest = i >> 5;
        const int nt = rest % 3; rest /= 3;
        const int ks = rest & 3;
        const int ch = rest >> 2;
        const int n = nt * 8 + (ln >> 2);
        const int k = ch * KC + ks * 8 + (ln & 3);
        uint32_t b0 = 0, b1 = 0;
        if (n < C) {
            b0 = f2tf32(centers[n * D + k]);
            b1 = f2tf32(centers[n * D + k + 4]);
        }
        Bf[i] = ((unsigned long long)b1 << 32) | b0;
    }
    // c2: 0.5*||center||^2 (fp32 exact); pad cols -> +huge (self-excluded from min)
    if (tid < 32) {
        float val = 1.0e30f;
        if (tid < C) {
            float s = 0.f;
            const float* cp = centers + tid * D;
            #pragma unroll 8
            for (int k = 0; k < D; k++) s = fmaf(cp[k], cp[k], s);
            val = 0.5f * s;
        }
        ((float*)(smemc + SM_C2))[tid] = val;
    }
    __syncthreads();

    const int use64 = *(const int*)(smemc + SM_FLAG);
    const float* c2s = (const float*)(smemc + SM_C2);
    float local = 0.f;

    if (wid == 16) {
        // ---------------- producer: one TMA per 32KB chunk ----------------
        if (lane == 0) {
            int st = 0, ph = 1;       // parity 1: first empty-wait passes on fresh barriers
            for (int t = bid; t < ntiles; t += GRID) {
                for (int ch = 0; ch < NCH; ch++) {
                    MBARRIER_WAIT_PARITY(sb + SM_EMPTY + st * 8, ph);
                    MBARRIER_EXPECT_TX(sb + SM_FULL + st * 8, STAGE_BYTES);
                    asm volatile(
                        "cp.async.bulk.tensor.2d.shared::cta.global.tile.mbarrier::complete_tx::bytes "
                        "[%0], [%1, {%2, %3}], [%4];"
                        :: "r"(sb + SM_A + st * STAGE_BYTES), "l"(&tmap),
                           "r"(ch * KC), "r"(t * TILE_M),
                           "r"(sb + SM_FULL + st * 8)
                        : "memory");
                    if (++st == S) { st = 0; ph ^= 1; }
                }
            }
        }
    } else {
        // -------- consumers: warp w owns rows [16w, 16w+16) of each 256-row tile ----
        const int r0 = wid * 16 + g4;      // fragment row (a0/a2), r1 = r0 + 8
        int st = 0, ph = 0;
        for (int t = bid; t < ntiles; t += GRID) {
            float d[3][4];
            #pragma unroll
            for (int nt = 0; nt < 3; nt++)
                #pragma unroll
                for (int e = 0; e < 4; e++) d[nt][e] = 0.f;

            for (int ch = 0; ch < NCH; ch++) {
                MBARRIER_WAIT_PARITY(sb + SM_FULL + st * 8, ph);
                const char* Ab = smemc + SM_A + st * STAGE_BYTES;
                #pragma unroll
                for (int ks = 0; ks < 4; ks++) {
                    const int ca = ks * 8 + q;     // col in chunk for a0/a1
                    uint32_t a0 = f2tf32(*(const float*)(Ab + SW128(r0 * 128 + ca * 4)));
                    uint32_t a1 = f2tf32(*(const float*)(Ab + SW128((r0 + 8) * 128 + ca * 4)));
                    uint32_t a2 = f2tf32(*(const float*)(Ab + SW128(r0 * 128 + (ca + 4) * 4)));
                    uint32_t a3 = f2tf32(*(const float*)(Ab + SW128((r0 + 8) * 128 + (ca + 4) * 4)));
                    const unsigned long long* bp = Bf + ((ch * 4 + ks) * 3) * 32 + lane;
                    #pragma unroll
                    for (int nt = 0; nt < 3; nt++) {
                        const unsigned long long bv = bp[nt * 32];   // LDS.64, conflict-free
                        mma_tf32(d[nt], a0, a1, a2, a3,
                                 (uint32_t)bv, (uint32_t)(bv >> 32));
                    }
                }
                __syncwarp();
                if (lane == 0) MBARRIER_ARRIVE(sb + SM_EMPTY + st * 8);
                if (++st == S) { st = 0; ph ^= 1; }
            }

            // ---- per-tile epilogue: rows rA = t*256 + r0, rB = rA + 8 ----
            const int rA = t * TILE_M + r0, rB = rA + 8;
            const int labA = use64 ? (int)((const long long*)labels)[rA]
                                   : ((const int*)labels)[rA];
            const int labB = use64 ? (int)((const long long*)labels)[rB]
                                   : ((const int*)labels)[rB];
            float posA = -3.0e38f, negA = 3.0e38f, posB = -3.0e38f, negB = 3.0e38f;
            #pragma unroll
            for (int nt = 0; nt < 3; nt++) {
                #pragma unroll
                for (int e = 0; e < 2; e++) {
                    const int col = nt * 8 + 2 * q + e;
                    const float c2v = c2s[col];
                    const float sA = c2v - d[nt][e];
                    const float sB = c2v - d[nt][2 + e];
                    if (col == labA) posA = sA; else negA = fminf(negA, sA);
                    if (col == labB) posB = sB; else negB = fminf(negB, sB);
                }
            }
            #pragma unroll
            for (int off = 1; off <= 2; off <<= 1) {
                posA = fmaxf(posA, __shfl_xor_sync(0xffffffffu, posA, off));
                negA = fminf(negA, __shfl_xor_sync(0xffffffffu, negA, off));
                posB = fmaxf(posB, __shfl_xor_sync(0xffffffffu, posB, off));
                negB = fminf(negB, __shfl_xor_sync(0xffffffffu, negB, off));
            }
            if (q == 0)
                local += fmaxf(0.f, posA + MARGIN_F - negA)
                       + fmaxf(0.f, posB + MARGIN_F - negB);
        }
    }

    // ---- block reduce (17 warps) + fused final reduction ----
    __syncthreads();
    float* wsum = (float*)(smemc + SM_WSUM);
    #pragma unroll
    for (int o = 16; o; o >>= 1) local += __shfl_down_sync(0xffffffffu, local, o);
    if (lane == 0) wsum[wid] = local;
    __syncthreads();
    if (tid == 0) {
        float bs = 0.f;
        #pragma unroll
        for (int w = 0; w < TPB / 32; w++) bs += wsum[w];
        g_partials[bid] = bs;
        __threadfence();
        unsigned int old = atomicAdd(&g_counter, 1u);
        is_last = (old == (unsigned)(gridDim.x - 1)) ? 1u : 0u;
    }
    __syncthreads();

    if (is_last) {
        float v = 0.f;
        for (int i = tid; i < (int)gridDim.x; i += TPB) v += g_partials[i];
        #pragma unroll
        for (int o = 16; o; o >>= 1) v += __shfl_down_sync(0xffffffffu, v, o);
        if (lane == 0) wsum[wid] = v;
        __syncthreads();
        if (tid == 0) {
            float tsum = 0.f;
            #pragma unroll
            for (int w = 0; w < TPB / 32; w++) tsum += wsum[w];
            out[0] = tsum / (float)Btot;
            g_counter = 0;     // reset for next graph replay
        }
    }
}

// ---------- host ----------
typedef CUresult (*PFN_encodeTiled)(CUtensorMap*, CUtensorMapDataType, cuuint32_t,
                                    void*, const cuuint64_t*, const cuuint64_t*,
                                    const cuuint32_t*, const cuuint32_t*,
                                    CUtensorMapInterleave, CUtensorMapSwizzle,
                                    CUtensorMapL2promotion, CUtensorMapFloatOOBfill);

extern "C" void kernel_launch(void* const* d_in, const int* in_sizes, int n_in,
                              void* d_out, int out_size) {
    // Identify inputs by element count: centers = C*D; labels = B; features = B*D.
    const float* cen = nullptr;
    for (int i = 0; i < n_in; i++)
        if (in_sizes[i] == C * D) cen = (const float*)d_in[i];

    int big = -1, small = -1;
    for (int i = 0; i < n_in; i++) {
        if ((const float*)d_in[i] == cen) continue;
        if (big < 0 || in_sizes[i] > in_sizes[big]) { small = big; big = i; }
        else small = i;
    }
    float*      feat = (float*)d_in[big];
    const void* lab  = d_in[small];
    int B = in_sizes[small];              // 65536
    int ntiles = B / TILE_M;              // 256

    // TMA tensormap via driver entry point (no -lcuda link needed)
    static PFN_encodeTiled encode_fn = nullptr;
    if (!encode_fn) {
        void* fn = nullptr;
        cudaDriverEntryPointQueryResult qr;
        cudaGetDriverEntryPoint("cuTensorMapEncodeTiled", &fn,
                                cudaEnableDefault, &qr);
        encode_fn = (PFN_encodeTiled)fn;
    }
    CUtensorMap tmap;
    {
        cuuint64_t dims[2]    = {(cuuint64_t)D, (cuuint64_t)B};
        cuuint64_t strides[1] = {(cuuint64_t)D * sizeof(float)};
        cuuint32_t box[2]     = {(cuuint32_t)KC, (cuuint32_t)TILE_M};
        cuuint32_t estr[2]    = {1, 1};
        encode_fn(&tmap, CU_TENSOR_MAP_DATA_TYPE_FLOAT32, 2, feat,
                  dims, strides, box, estr,
                  CU_TENSOR_MAP_INTERLEAVE_NONE, CU_TENSOR_MAP_SWIZZLE_128B,
                  CU_TENSOR_MAP_L2_PROMOTION_L2_128B,
                  CU_TENSOR_MAP_FLOAT_OOB_FILL_NONE);
    }

    static int attr_set = 0;
    if (!attr_set) {
        cudaFuncSetAttribute(tcl_mma_kernel, cudaFuncAttributeMaxDynamicSharedMemorySize,
                             SMEM_TOTAL);
        attr_set = 1;
    }

    tcl_mma_kernel<<<GRID, TPB, SMEM_TOTAL>>>(tmap, cen, lab, (float*)d_out, B, ntiles);
}